// round 14
// baseline (speedup 1.0000x reference)
#include <cuda_runtime.h>
#include <cuda_fp16.h>
#include <cstdint>

#define TT 1024
#define HH 16
#define SS 8192
#define DKA 128     // absorbed dims
#define DR 64       // rope dims
#define DV 128
#define LORA 512
#define KV_W 576
#define SN 32
#define NT (SS / SN)
#define QSCALE 0.1041216338861046f    // (1/sqrt(192)) * log2(e)

// fp16 inputs + projected operands
__device__ __half g_kvh[(size_t)SS * KV_W];
__device__ __half g_wkh[(size_t)HH * DKA * LORA];
__device__ __half g_wvh[(size_t)HH * LORA * DV];
__device__ __half g_Rh[(size_t)SS * DR];         // shared rope K
__device__ __half g_K[(size_t)HH * SS * DKA];    // absorbed K
__device__ __half g_V[(size_t)HH * SS * DV];     // absorbed V

// ===================== helpers =====================
__device__ __forceinline__ uint32_t smem_u32(const void* p) {
    uint32_t a;
    asm("{ .reg .u64 t; cvta.to.shared.u64 t, %1; cvt.u32.u64 %0, t; }" : "=r"(a) : "l"(p));
    return a;
}
__device__ __forceinline__ void ldsm4(uint32_t* r, uint32_t a) {
    asm volatile("ldmatrix.sync.aligned.m8n8.x4.shared.b16 {%0,%1,%2,%3}, [%4];"
        : "=r"(r[0]), "=r"(r[1]), "=r"(r[2]), "=r"(r[3]) : "r"(a));
}
__device__ __forceinline__ void ldsm4t(uint32_t* r, uint32_t a) {
    asm volatile("ldmatrix.sync.aligned.m8n8.x4.trans.shared.b16 {%0,%1,%2,%3}, [%4];"
        : "=r"(r[0]), "=r"(r[1]), "=r"(r[2]), "=r"(r[3]) : "r"(a));
}
__device__ __forceinline__ void mma16816h(float* d, const uint32_t* a, const uint32_t* b) {
    asm volatile("mma.sync.aligned.m16n8k16.row.col.f32.f16.f16.f32 "
        "{%0,%1,%2,%3}, {%4,%5,%6,%7}, {%8,%9}, {%0,%1,%2,%3};"
        : "+f"(d[0]), "+f"(d[1]), "+f"(d[2]), "+f"(d[3])
        : "r"(a[0]), "r"(a[1]), "r"(a[2]), "r"(a[3]), "r"(b[0]), "r"(b[1]));
}
__device__ __forceinline__ float ex2f(float x) {
    float r;
    asm("ex2.approx.f32 %0, %1;" : "=f"(r) : "f"(x));
    return r;
}
__device__ __forceinline__ void cp16(uint32_t dst, const void* src) {
    asm volatile("cp.async.cg.shared.global [%0], [%1], 16;" :: "r"(dst), "l"(src));
}
#define CP_COMMIT() asm volatile("cp.async.commit_group;" ::: "memory")
#define CP_WAIT0()  asm volatile("cp.async.wait_group 0;" ::: "memory")
#define CP_WAIT2()  asm volatile("cp.async.wait_group 2;" ::: "memory")

// ===================== split kernel (fp32 -> fp16) =====================
#define N1 (SS * KV_W / 4)
#define N2 (HH * DKA * LORA / 4)
#define N3 (HH * LORA * DV / 4)

__global__ __launch_bounds__(256)
void split_kernel(const float* __restrict__ kv, const float* __restrict__ wk,
                  const float* __restrict__ wv) {
    const int i = blockIdx.x * 256 + threadIdx.x;
    if (i < N1) {
        float4 v = ((const float4*)kv)[i];
        __half2 a = __floats2half2_rn(v.x, v.y);
        __half2 b = __floats2half2_rn(v.z, v.w);
        ((__half2*)g_kvh)[2 * i] = a; ((__half2*)g_kvh)[2 * i + 1] = b;
        int c = (i * 4) % KV_W;
        if (c >= LORA) {
            int s = (i * 4) / KV_W;
            int o = s * DR + (c - LORA);
            ((__half2*)g_Rh)[o / 2]     = a;
            ((__half2*)g_Rh)[o / 2 + 1] = b;
        }
    } else if (i < N1 + N2) {
        int j = i - N1;
        float4 v = ((const float4*)wk)[j];
        __half2 a = __floats2half2_rn(v.x, v.y);
        __half2 b = __floats2half2_rn(v.z, v.w);
        ((__half2*)g_wkh)[2 * j] = a; ((__half2*)g_wkh)[2 * j + 1] = b;
    } else if (i < N1 + N2 + N3) {
        int j = i - N1 - N2;
        float4 v = ((const float4*)wv)[j];
        __half2 a = __floats2half2_rn(v.x, v.y);
        __half2 b = __floats2half2_rn(v.z, v.w);
        ((__half2*)g_wvh)[2 * j] = a; ((__half2*)g_wvh)[2 * j + 1] = b;
    }
}

// ========== fused projection: 128 rows/CTA, k64 chunks, 1 barrier/chunk =====
//  g_K[h,s,:] = kv_lora[s,:] . w_kc[h,:,:]^T   (accK)
//  g_V[h,s,:] = kv_lora[s,:] . w_vc[h,:,:]     (accV)
#define PASTR 144                            // 64 fp16 + 16B pad
#define PJ_A  0
#define PJ_BK (128 * PASTR)                  // 18432
#define PJ_BV (2 * 128 * PASTR)              // 36864
#define PJ_BVSTR 272
#define PJ_STAGE (PJ_BV + 64 * PJ_BVSTR)     // 54272
#define PJ_SMEM (2 * PJ_STAGE)               // 108544

__global__ __launch_bounds__(256)
void proj_fused() {
    extern __shared__ __align__(16) char smp[];
    const uint32_t sb = smem_u32(smp);
    const int tid = threadIdx.x, lane = tid & 31, wp = tid >> 5;
    const int grp = lane >> 2, tg = lane & 3;
    const int h = blockIdx.y, s0 = blockIdx.x * 128;

    const __half* Akv = g_kvh + (size_t)s0 * KV_W;
    const __half* BK  = g_wkh + (size_t)h * DKA * LORA;
    const __half* BV  = g_wvh + (size_t)h * LORA * DV;
    const int lr = tid >> 1;                 // A/BK rows (2 threads per row)
    const int vr = tid >> 2;                 // BV k-rows (4 threads per row)

    #define PJ_LOAD(stage, kt) do { \
        uint32_t base_ = sb + (uint32_t)(stage) * PJ_STAGE; \
        _Pragma("unroll") \
        for (int j_ = 0; j_ < 4; j_++) { \
            int c16_ = (tid & 1) * 4 + j_; \
            cp16(base_ + PJ_A  + lr * PASTR + c16_ * 16, Akv + (size_t)lr * KV_W + (kt) + c16_ * 8); \
            cp16(base_ + PJ_BK + lr * PASTR + c16_ * 16, BK  + (size_t)lr * LORA + (kt) + c16_ * 8); \
            int b16_ = (tid & 3) * 4 + j_; \
            cp16(base_ + PJ_BV + vr * PJ_BVSTR + b16_ * 16, BV + (size_t)((kt) + vr) * DV + b16_ * 8); \
        } \
    } while (0)

    PJ_LOAD(0, 0);
    CP_COMMIT();

    float accK[16][4], accV[16][4];
    #pragma unroll
    for (int i = 0; i < 16; i++)
        #pragma unroll
        for (int j = 0; j < 4; j++) { accK[i][j] = 0.f; accV[i][j] = 0.f; }

    const uint32_t aoff  = (uint32_t)((wp * 16 + (lane & 15)) * PASTR + (lane >> 4) * 16);
    const uint32_t bkoff = (uint32_t)(((lane & 7) + ((lane >> 4) & 1) * 8) * PASTR + ((lane >> 3) & 1) * 16);
    const uint32_t bvoff = (uint32_t)(((lane & 7) + ((lane >> 3) & 1) * 8) * PJ_BVSTR + ((lane >> 4) & 1) * 16);

    for (int c = 0; c < 8; c++) {
        CP_WAIT0();          // chunk c's data ready
        __syncthreads();     // all warps done reading the OTHER stage (chunk c-1)
        if (c + 1 < 8) {
            PJ_LOAD((c + 1) & 1, (c + 1) * 64);
            CP_COMMIT();     // global fetch overlaps compute below
        }
        const uint32_t base = sb + (uint32_t)(c & 1) * PJ_STAGE;
        #pragma unroll
        for (int ks = 0; ks < 4; ks++) {
            uint32_t a[4];
            ldsm4(a, base + PJ_A + aoff + ks * 32);
            #pragma unroll
            for (int np = 0; np < 8; np++) {
                uint32_t bk[4], bv[4];
                ldsm4(bk, base + PJ_BK + bkoff + np * 16 * PASTR + ks * 32);
                mma16816h(accK[np * 2],     a, bk);
                mma16816h(accK[np * 2 + 1], a, bk + 2);
                ldsm4t(bv, base + PJ_BV + bvoff + ks * 16 * PJ_BVSTR + np * 32);
                mma16816h(accV[np * 2],     a, bv);
                mma16816h(accV[np * 2 + 1], a, bv + 2);
            }
        }
    }

    const int r0 = s0 + wp * 16 + grp, r1 = r0 + 8;
    #pragma unroll
    for (int nb = 0; nb < 16; nb++) {
        int col = nb * 8 + tg * 2;
        __half2 k0 = __floats2half2_rn(accK[nb][0], accK[nb][1]);
        __half2 k1 = __floats2half2_rn(accK[nb][2], accK[nb][3]);
        *(__half2*)(g_K + ((size_t)h * SS + r0) * DKA + col) = k0;
        *(__half2*)(g_K + ((size_t)h * SS + r1) * DKA + col) = k1;
        __half2 v0 = __floats2half2_rn(accV[nb][0], accV[nb][1]);
        __half2 v1 = __floats2half2_rn(accV[nb][2], accV[nb][3]);
        *(__half2*)(g_V + ((size_t)h * SS + r0) * DV + col) = v0;
        *(__half2*)(g_V + ((size_t)h * SS + r1) * DV + col) = v1;
    }
}

// ====== attention: 64q CTAs, 4 slots, 1 barrier/tile, FADD rsum ============
#define QROWS 64
#define KSTR2 400
#define VSTR2 272                       // 128 V cols + pad
#define AT_K 0
#define AT_V (SN * KSTR2)               // 12800
#define AT_STG (AT_V + SN * VSTR2)      // 21504
#define AT_Q (2 * AT_STG)               // Q overlay in slots 2-3 region
#define AT_SMEM (4 * AT_STG)            // 86016

__device__ __forceinline__ void load_stage(uint32_t sb, int h, int s0, int slot, int tid) {
    const uint32_t base = sb + (uint32_t)slot * AT_STG;
    const __half* gk = g_K + ((size_t)h * SS + s0) * DKA;
    const __half* gr = g_Rh + (size_t)s0 * DR;
    const __half* gv = g_V + ((size_t)h * SS + s0) * DV;
    #pragma unroll
    for (int i = 0; i < 6; i++) {
        int idx = tid + i * 128;
        int r = idx / 24, c = idx - r * 24;
        if (c < 16) cp16(base + AT_K + r * KSTR2 + c * 16, gk + (size_t)r * DKA + c * 8);
        else        cp16(base + AT_K + r * KSTR2 + c * 16, gr + (size_t)r * DR + (c - 16) * 8);
    }
    #pragma unroll
    for (int i = 0; i < 4; i++) {
        int idx = tid + i * 128;
        int r = idx >> 4, c = idx & 15;
        cp16(base + AT_V + r * VSTR2 + c * 16, gv + (size_t)r * DV + c * 8);
    }
}

__global__ __launch_bounds__(128, 2)
void attn_mma(const float* __restrict__ q, float* __restrict__ out) {
    extern __shared__ __align__(16) char sma[];
    const uint32_t sb = smem_u32(sma);
    const int tid = threadIdx.x, lane = tid & 31, wp = tid >> 5;
    const int grp = lane >> 2, tg = lane & 3;
    const int h = blockIdx.y, t0 = blockIdx.x * QROWS;

    // slots 0,1 first (independent of Q staging)
    load_stage(sb, h, 0, 0, tid); CP_COMMIT();
    load_stage(sb, h, SN, 1, tid); CP_COMMIT();

    // Q: scale by QSCALE, round fp16, stage in slots 2-3 overlay region
    {
        const int r = tid >> 1, half = tid & 1;
        const float* qp = q + (size_t)(t0 + r) * (HH * (DKA + DR)) + (size_t)h * (DKA + DR) + half * 96;
        uint32_t* pH = (uint32_t*)(sma + AT_Q + r * KSTR2 + half * 192);
        #pragma unroll
        for (int i = 0; i < 24; i++) {
            float4 v = *(const float4*)(qp + i * 4);
            __half2 a = __floats2half2_rn(v.x * QSCALE, v.y * QSCALE);
            __half2 b = __floats2half2_rn(v.z * QSCALE, v.w * QSCALE);
            pH[2 * i]     = *(uint32_t*)&a;
            pH[2 * i + 1] = *(uint32_t*)&b;
        }
    }
    __syncthreads();

    uint32_t qf[12][4];
    {
        const uint32_t qa = sb + AT_Q + (uint32_t)((wp * 16 + (lane & 15)) * KSTR2 + (lane >> 4) * 16);
        #pragma unroll
        for (int ks = 0; ks < 12; ks++) ldsm4(qf[ks], qa + ks * 32);
    }
    // all warps must finish reading Q fragments before cp.async prefetch
    // into slots 2-3 (below) overwrites the Q overlay region.
    __syncthreads();

    load_stage(sb, h, 2 * SN, 2, tid); CP_COMMIT();

    float O[16][4];
    #pragma unroll
    for (int i = 0; i < 16; i++)
        #pragma unroll
        for (int j = 0; j < 4; j++) O[i][j] = 0.f;
    float rs0 = 0.f, rs1 = 0.f;

    const uint32_t kboff = (uint32_t)(((lane & 7) + ((lane >> 4) & 1) * 8) * KSTR2 + ((lane >> 3) & 1) * 16);
    const uint32_t vboff = (uint32_t)(((lane & 7) + ((lane >> 3) & 1) * 8) * VSTR2 + ((lane >> 4) & 1) * 16);

    for (int t = 0; t < NT; t++) {
        CP_WAIT2();
        __syncthreads();
        const uint32_t base = sb + (uint32_t)(t & 3) * AT_STG;

        // MMA1: scores (log2-domain; QSCALE folded in)
        float S[4][4];
        #pragma unroll
        for (int i = 0; i < 4; i++)
            #pragma unroll
            for (int j = 0; j < 4; j++) S[i][j] = 0.f;

        #pragma unroll
        for (int ks = 0; ks < 12; ks++) {
            #pragma unroll
            for (int np = 0; np < 2; np++) {
                uint32_t b[4];
                ldsm4(b, base + AT_K + kboff + np * 16 * KSTR2 + ks * 32);
                mma16816h(S[np * 2],     qf[ks], b);
                mma16816h(S[np * 2 + 1], qf[ks], b + 2);
            }
        }

        // softmax: p = 2^S in fp32 (MUFU) + FADD rsum; pack to fp16 A frags
        uint32_t ph[2][4];
        #pragma unroll
        for (int kk = 0; kk < 2; kk++) {
            #pragma unroll
            for (int sub = 0; sub < 2; sub++) {
                float* c = S[2 * kk + sub];
                float e0 = ex2f(c[0]);
                float e1 = ex2f(c[1]);
                float e2 = ex2f(c[2]);
                float e3 = ex2f(c[3]);
                rs0 += e0 + e1;
                rs1 += e2 + e3;
                __half2 p0 = __floats2half2_rn(e0, e1);
                __half2 p1 = __floats2half2_rn(e2, e3);
                ph[kk][sub * 2]     = *(uint32_t*)&p0;
                ph[kk][sub * 2 + 1] = *(uint32_t*)&p1;
            }
        }

        // MMA2: O += P * V
        #pragma unroll
        for (int kk = 0; kk < 2; kk++) {
            #pragma unroll
            for (int np = 0; np < 8; np++) {
                uint32_t v[4];
                ldsm4t(v, base + AT_V + vboff + kk * 16 * VSTR2 + np * 32);
                mma16816h(O[np * 2],     ph[kk], v);
                mma16816h(O[np * 2 + 1], ph[kk], v + 2);
            }
        }
        // no tail barrier: top-of-tile barrier at t proves all warps finished t-1,
        // and slot (t+3)&3 == (t-1)&3 was last read at t-1.
        if (t + 3 < NT) load_stage(sb, h, (t + 3) * SN, (t + 3) & 3, tid);
        CP_COMMIT();
    }

    // reduce row sums across the quad (lanes sharing a row)
    rs0 += __shfl_xor_sync(0xffffffffu, rs0, 1);
    rs0 += __shfl_xor_sync(0xffffffffu, rs0, 2);
    rs1 += __shfl_xor_sync(0xffffffffu, rs1, 1);
    rs1 += __shfl_xor_sync(0xffffffffu, rs1, 2);
    const float i0 = 1.0f / rs0, i1 = 1.0f / rs1;

    const int r0 = t0 + wp * 16 + grp, r1 = r0 + 8;
    #pragma unroll
    for (int nb = 0; nb < 16; nb++) {
        const int col = h * DV + nb * 8 + tg * 2;
        float2 v0 = make_float2(O[nb][0] * i0, O[nb][1] * i0);
        float2 v1 = make_float2(O[nb][2] * i1, O[nb][3] * i1);
        *(float2*)(out + (size_t)r0 * (HH * DV) + col) = v0;
        *(float2*)(out + (size_t)r1 * (HH * DV) + col) = v1;
    }
}

// ===================== launch =====================
extern "C" void kernel_launch(void* const* d_in, const int* in_sizes, int n_in,
                              void* d_out, int out_size) {
    const float* q    = (const float*)d_in[0];   // (1024, 16, 192)
    const float* kv   = (const float*)d_in[1];   // (8192, 576)
    const float* w_kc = (const float*)d_in[2];   // (16, 128, 512)
    const float* w_vc = (const float*)d_in[3];   // (16, 512, 128)
    float* out = (float*)d_out;                  // (1024, 2048)
    (void)in_sizes; (void)n_in; (void)out_size;

    cudaFuncSetAttribute(proj_fused, cudaFuncAttributeMaxDynamicSharedMemorySize, PJ_SMEM);
    cudaFuncSetAttribute(attn_mma, cudaFuncAttributeMaxDynamicSharedMemorySize, AT_SMEM);

    split_kernel<<<(N1 + N2 + N3 + 255) / 256, 256>>>(kv, w_kc, w_vc);

    dim3 pgrid(SS / 128, HH);   // (64, 16) = 1024 CTAs
    proj_fused<<<pgrid, 256, PJ_SMEM>>>();

    dim3 agrid(TT / QROWS, HH);   // (16, 16) = 256 CTAs
    attn_mma<<<agrid, 128, AT_SMEM>>>(q, out);
}

// round 15
// speedup vs baseline: 1.0242x; 1.0242x over previous
#include <cuda_runtime.h>
#include <cuda_fp16.h>
#include <cstdint>

#define TT 1024
#define HH 16
#define SS 8192
#define DKA 128     // absorbed dims
#define DR 64       // rope dims
#define DV 128
#define LORA 512
#define KV_W 576
#define SN 32
#define NSPLIT 2
#define SHALF (SS / NSPLIT)
#define NT2 (SHALF / SN)               // 128 tiles per CTA
#define QSCALE 0.1041216338861046f    // (1/sqrt(192)) * log2(e)

// fp16 inputs + projected operands
__device__ __half g_kvh[(size_t)SS * KV_W];
__device__ __half g_wkh[(size_t)HH * DKA * LORA];
__device__ __half g_wvh[(size_t)HH * LORA * DV];
__device__ __half g_Rh[(size_t)SS * DR];         // shared rope K
__device__ __half g_K[(size_t)HH * SS * DKA];    // absorbed K
__device__ __half g_V[(size_t)HH * SS * DV];     // absorbed V
// split-attention partials
__device__ float g_Op[NSPLIT][(size_t)TT * HH * DV];   // unnormalized O
__device__ float g_rp[NSPLIT][(size_t)HH * TT];        // row sums

// ===================== helpers =====================
__device__ __forceinline__ uint32_t smem_u32(const void* p) {
    uint32_t a;
    asm("{ .reg .u64 t; cvta.to.shared.u64 t, %1; cvt.u32.u64 %0, t; }" : "=r"(a) : "l"(p));
    return a;
}
__device__ __forceinline__ void ldsm4(uint32_t* r, uint32_t a) {
    asm volatile("ldmatrix.sync.aligned.m8n8.x4.shared.b16 {%0,%1,%2,%3}, [%4];"
        : "=r"(r[0]), "=r"(r[1]), "=r"(r[2]), "=r"(r[3]) : "r"(a));
}
__device__ __forceinline__ void ldsm4t(uint32_t* r, uint32_t a) {
    asm volatile("ldmatrix.sync.aligned.m8n8.x4.trans.shared.b16 {%0,%1,%2,%3}, [%4];"
        : "=r"(r[0]), "=r"(r[1]), "=r"(r[2]), "=r"(r[3]) : "r"(a));
}
__device__ __forceinline__ void mma16816h(float* d, const uint32_t* a, const uint32_t* b) {
    asm volatile("mma.sync.aligned.m16n8k16.row.col.f32.f16.f16.f32 "
        "{%0,%1,%2,%3}, {%4,%5,%6,%7}, {%8,%9}, {%0,%1,%2,%3};"
        : "+f"(d[0]), "+f"(d[1]), "+f"(d[2]), "+f"(d[3])
        : "r"(a[0]), "r"(a[1]), "r"(a[2]), "r"(a[3]), "r"(b[0]), "r"(b[1]));
}
__device__ __forceinline__ float ex2f(float x) {
    float r;
    asm("ex2.approx.f32 %0, %1;" : "=f"(r) : "f"(x));
    return r;
}
__device__ __forceinline__ void cp16(uint32_t dst, const void* src) {
    asm volatile("cp.async.cg.shared.global [%0], [%1], 16;" :: "r"(dst), "l"(src));
}
#define CP_COMMIT() asm volatile("cp.async.commit_group;" ::: "memory")
#define CP_WAIT0()  asm volatile("cp.async.wait_group 0;" ::: "memory")
#define CP_WAIT1()  asm volatile("cp.async.wait_group 1;" ::: "memory")
#define CP_WAIT2()  asm volatile("cp.async.wait_group 2;" ::: "memory")

// ===================== split kernel (fp32 -> fp16) =====================
#define N1 (SS * KV_W / 4)
#define N2 (HH * DKA * LORA / 4)
#define N3 (HH * LORA * DV / 4)

__global__ __launch_bounds__(256)
void split_kernel(const float* __restrict__ kv, const float* __restrict__ wk,
                  const float* __restrict__ wv) {
    const int i = blockIdx.x * 256 + threadIdx.x;
    if (i < N1) {
        float4 v = ((const float4*)kv)[i];
        __half2 a = __floats2half2_rn(v.x, v.y);
        __half2 b = __floats2half2_rn(v.z, v.w);
        ((__half2*)g_kvh)[2 * i] = a; ((__half2*)g_kvh)[2 * i + 1] = b;
        int c = (i * 4) % KV_W;
        if (c >= LORA) {
            int s = (i * 4) / KV_W;
            int o = s * DR + (c - LORA);
            ((__half2*)g_Rh)[o / 2]     = a;
            ((__half2*)g_Rh)[o / 2 + 1] = b;
        }
    } else if (i < N1 + N2) {
        int j = i - N1;
        float4 v = ((const float4*)wk)[j];
        __half2 a = __floats2half2_rn(v.x, v.y);
        __half2 b = __floats2half2_rn(v.z, v.w);
        ((__half2*)g_wkh)[2 * j] = a; ((__half2*)g_wkh)[2 * j + 1] = b;
    } else if (i < N1 + N2 + N3) {
        int j = i - N1 - N2;
        float4 v = ((const float4*)wv)[j];
        __half2 a = __floats2half2_rn(v.x, v.y);
        __half2 b = __floats2half2_rn(v.z, v.w);
        ((__half2*)g_wvh)[2 * j] = a; ((__half2*)g_wvh)[2 * j + 1] = b;
    }
}

// ========== fused projection (round-10 exact): shares the kv_lora A tile ====
#define PSTR 80
#define PJ_A  0
#define PJ_BK (128 * PSTR)                  // 10240
#define PJ_BV (2 * 128 * PSTR)              // 20480
#define PJ_BVSTR 272
#define PJ_STAGE (PJ_BV + 32 * PJ_BVSTR)    // 29184
#define PJ_SMEM (2 * PJ_STAGE)              // 58368

__global__ __launch_bounds__(256)
void proj_fused() {
    extern __shared__ __align__(16) char smp[];
    const uint32_t sb = smem_u32(smp);
    const int tid = threadIdx.x, lane = tid & 31, wp = tid >> 5;
    const int grp = lane >> 2, tg = lane & 3;
    const int h = blockIdx.y, s0 = blockIdx.x * 128;

    const __half* Akv = g_kvh + (size_t)s0 * KV_W;
    const __half* BK  = g_wkh + (size_t)h * DKA * LORA;
    const __half* BV  = g_wvh + (size_t)h * LORA * DV;
    const int lr = tid >> 1;
    const int br = tid >> 3, bcb = (tid & 7) * 2;

    #define PJ_LOAD(stage, kt) do { \
        uint32_t base_ = sb + (stage) * PJ_STAGE; \
        _Pragma("unroll") \
        for (int j_ = 0; j_ < 2; j_++) { \
            int c16_ = (tid & 1) * 2 + j_; \
            cp16(base_ + PJ_A  + lr * PSTR + c16_ * 16, Akv + (size_t)lr * KV_W + (kt) + c16_ * 8); \
            cp16(base_ + PJ_BK + lr * PSTR + c16_ * 16, BK  + (size_t)lr * LORA + (kt) + c16_ * 8); \
            int b16_ = bcb + j_; \
            cp16(base_ + PJ_BV + br * PJ_BVSTR + b16_ * 16, BV + (size_t)((kt) + br) * DV + b16_ * 8); \
        } \
    } while (0)

    PJ_LOAD(0, 0); CP_COMMIT();

    float accK[16][4], accV[16][4];
    #pragma unroll
    for (int i = 0; i < 16; i++)
        #pragma unroll
        for (int j = 0; j < 4; j++) { accK[i][j] = 0.f; accV[i][j] = 0.f; }

    const uint32_t aoff  = (uint32_t)((wp * 16 + (lane & 15)) * PSTR + (lane >> 4) * 16);
    const uint32_t bkoff = (uint32_t)(((lane & 7) + ((lane >> 4) & 1) * 8) * PSTR + ((lane >> 3) & 1) * 16);
    const uint32_t bvoff = (uint32_t)(((lane & 7) + ((lane >> 3) & 1) * 8) * PJ_BVSTR + ((lane >> 4) & 1) * 16);

    for (int c = 0; c < 16; c++) {
        if (c + 1 < 16) { PJ_LOAD((c + 1) & 1, (c + 1) * 32); CP_COMMIT(); CP_WAIT1(); }
        else { CP_WAIT0(); }
        __syncthreads();
        const uint32_t base = sb + (c & 1) * PJ_STAGE;
        #pragma unroll
        for (int ks = 0; ks < 2; ks++) {
            uint32_t a[4];
            ldsm4(a, base + PJ_A + aoff + ks * 32);
            #pragma unroll
            for (int np = 0; np < 8; np++) {
                uint32_t bk[4], bv[4];
                ldsm4(bk, base + PJ_BK + bkoff + np * 16 * PSTR + ks * 32);
                mma16816h(accK[np * 2],     a, bk);
                mma16816h(accK[np * 2 + 1], a, bk + 2);
                ldsm4t(bv, base + PJ_BV + bvoff + ks * 16 * PJ_BVSTR + np * 32);
                mma16816h(accV[np * 2],     a, bv);
                mma16816h(accV[np * 2 + 1], a, bv + 2);
            }
        }
        __syncthreads();
    }

    const int r0 = s0 + wp * 16 + grp, r1 = r0 + 8;
    #pragma unroll
    for (int nb = 0; nb < 16; nb++) {
        int col = nb * 8 + tg * 2;
        __half2 k0 = __floats2half2_rn(accK[nb][0], accK[nb][1]);
        __half2 k1 = __floats2half2_rn(accK[nb][2], accK[nb][3]);
        *(__half2*)(g_K + ((size_t)h * SS + r0) * DKA + col) = k0;
        *(__half2*)(g_K + ((size_t)h * SS + r1) * DKA + col) = k1;
        __half2 v0 = __floats2half2_rn(accV[nb][0], accV[nb][1]);
        __half2 v1 = __floats2half2_rn(accV[nb][2], accV[nb][3]);
        *(__half2*)(g_V + ((size_t)h * SS + r0) * DV + col) = v0;
        *(__half2*)(g_V + ((size_t)h * SS + r1) * DV + col) = v1;
    }
}

// ====== attention (round-10 body + key-range split, partial outputs) ========
#define QROWS 64
#define KSTR2 400
#define VSTR2 304                       // 144 cols (128 V + ones + pad)
#define AT_K 0
#define AT_V (SN * KSTR2)               // 12800
#define AT_STG (AT_V + SN * VSTR2)      // 22528
#define AT_Q (2 * AT_STG)               // Q overlay in slots 2-3 region
#define AT_SMEM (4 * AT_STG)            // 90112

__device__ __forceinline__ void load_stage(uint32_t sb, int h, int s0, int slot, int tid) {
    const uint32_t base = sb + (uint32_t)slot * AT_STG;
    const __half* gk = g_K + ((size_t)h * SS + s0) * DKA;
    const __half* gr = g_Rh + (size_t)s0 * DR;
    const __half* gv = g_V + ((size_t)h * SS + s0) * DV;
    #pragma unroll
    for (int i = 0; i < 6; i++) {
        int idx = tid + i * 128;
        int r = idx / 24, c = idx - r * 24;
        if (c < 16) cp16(base + AT_K + r * KSTR2 + c * 16, gk + (size_t)r * DKA + c * 8);
        else        cp16(base + AT_K + r * KSTR2 + c * 16, gr + (size_t)r * DR + (c - 16) * 8);
    }
    #pragma unroll
    for (int i = 0; i < 4; i++) {
        int idx = tid + i * 128;
        int r = idx >> 4, c = idx & 15;
        cp16(base + AT_V + r * VSTR2 + c * 16, gv + (size_t)r * DV + c * 8);
    }
}

__global__ __launch_bounds__(128, 2)
void attn_mma(const float* __restrict__ q) {
    extern __shared__ __align__(16) char sma[];
    const uint32_t sb = smem_u32(sma);
    const int tid = threadIdx.x, lane = tid & 31, wp = tid >> 5;
    const int grp = lane >> 2, tg = lane & 3;
    const int h = blockIdx.y, t0 = blockIdx.x * QROWS;
    const int z = blockIdx.z;
    const int ks0 = z * SHALF;            // key-range base for this split

    // slots 0,1 first (independent of Q staging)
    load_stage(sb, h, ks0, 0, tid); CP_COMMIT();
    load_stage(sb, h, ks0 + SN, 1, tid); CP_COMMIT();

    // Q: scale by QSCALE, round fp16, stage in slots 2-3 overlay region
    {
        const int r = tid >> 1, half = tid & 1;
        const float* qp = q + (size_t)(t0 + r) * (HH * (DKA + DR)) + (size_t)h * (DKA + DR) + half * 96;
        uint32_t* pH = (uint32_t*)(sma + AT_Q + r * KSTR2 + half * 192);
        #pragma unroll
        for (int i = 0; i < 24; i++) {
            float4 v = *(const float4*)(qp + i * 4);
            __half2 a = __floats2half2_rn(v.x * QSCALE, v.y * QSCALE);
            __half2 b = __floats2half2_rn(v.z * QSCALE, v.w * QSCALE);
            pH[2 * i]     = *(uint32_t*)&a;
            pH[2 * i + 1] = *(uint32_t*)&b;
        }
    }
    __syncthreads();

    uint32_t qf[12][4];
    {
        const uint32_t qa = sb + AT_Q + (uint32_t)((wp * 16 + (lane & 15)) * KSTR2 + (lane >> 4) * 16);
        #pragma unroll
        for (int ks = 0; ks < 12; ks++) ldsm4(qf[ks], qa + ks * 32);
    }
    // all warps must finish reading Q fragments before the ones-init below
    // overwrites parts of the Q overlay region.
    __syncthreads();

    // ones-column init: all 4 slots, V cols 128..143 (col 128 = 1.0)
    {
        const __half2 one0 = __halves2half2(__float2half(1.f), __float2half(0.f));
        const __half2 zero = __halves2half2(__float2half(0.f), __float2half(0.f));
        #pragma unroll
        for (int i = 0; i < 8; i++) {
            int idx = tid + i * 128;           // 1024 = 4 slots * 32 rows * 8 half2
            int slot = idx >> 8;
            int rem = idx & 255;
            int r = rem >> 3, c2 = rem & 7;
            *(__half2*)(sma + slot * AT_STG + AT_V + r * VSTR2 + 256 + c2 * 4)
                = (c2 == 0) ? one0 : zero;
        }
    }
    __syncthreads();

    load_stage(sb, h, ks0 + 2 * SN, 2, tid); CP_COMMIT();

    float O[18][4];
    #pragma unroll
    for (int i = 0; i < 18; i++)
        #pragma unroll
        for (int j = 0; j < 4; j++) O[i][j] = 0.f;

    const uint32_t kboff = (uint32_t)(((lane & 7) + ((lane >> 4) & 1) * 8) * KSTR2 + ((lane >> 3) & 1) * 16);
    const uint32_t vboff = (uint32_t)(((lane & 7) + ((lane >> 3) & 1) * 8) * VSTR2 + ((lane >> 4) & 1) * 16);

    for (int t = 0; t < NT2; t++) {
        CP_WAIT2();
        __syncthreads();
        const uint32_t base = sb + (uint32_t)(t & 3) * AT_STG;

        // MMA1: scores (log2-domain; QSCALE folded in)
        float S[4][4];
        #pragma unroll
        for (int i = 0; i < 4; i++)
            #pragma unroll
            for (int j = 0; j < 4; j++) S[i][j] = 0.f;

        #pragma unroll
        for (int ks = 0; ks < 12; ks++) {
            #pragma unroll
            for (int np = 0; np < 2; np++) {
                uint32_t b[4];
                ldsm4(b, base + AT_K + kboff + np * 16 * KSTR2 + ks * 32);
                mma16816h(S[np * 2],     qf[ks], b);
                mma16816h(S[np * 2 + 1], qf[ks], b + 2);
            }
        }

        // softmax: p = 2^S in fp32 (MUFU), then pack to fp16 A-fragments
        uint32_t ph[2][4];
        #pragma unroll
        for (int kk = 0; kk < 2; kk++) {
            #pragma unroll
            for (int sub = 0; sub < 2; sub++) {
                float* c = S[2 * kk + sub];
                float e0 = ex2f(c[0]);
                float e1 = ex2f(c[1]);
                float e2 = ex2f(c[2]);
                float e3 = ex2f(c[3]);
                __half2 p0 = __floats2half2_rn(e0, e1);
                __half2 p1 = __floats2half2_rn(e2, e3);
                ph[kk][sub * 2]     = *(uint32_t*)&p0;
                ph[kk][sub * 2 + 1] = *(uint32_t*)&p1;
            }
        }

        // MMA2: O += P * V  (np=8 block carries the ones column -> row sums)
        #pragma unroll
        for (int kk = 0; kk < 2; kk++) {
            #pragma unroll
            for (int np = 0; np < 9; np++) {
                uint32_t v[4];
                ldsm4t(v, base + AT_V + vboff + kk * 16 * VSTR2 + np * 32);
                mma16816h(O[np * 2],     ph[kk], v);
                mma16816h(O[np * 2 + 1], ph[kk], v + 2);
            }
        }
        // no tail barrier: top-of-tile barrier at t proves all warps finished t-1,
        // and slot (t+3)&3 == (t-1)&3 was last read at t-1.
        if (t + 3 < NT2) load_stage(sb, h, ks0 + (t + 3) * SN, (t + 3) & 3, tid);
        CP_COMMIT();
    }

    // row sums from the tensor-core ones-column: block 16, col 128
    const float r0s = __shfl_sync(0xffffffffu, O[16][0], lane & ~3);
    const float r1s = __shfl_sync(0xffffffffu, O[16][2], lane & ~3);

    const int r0 = t0 + wp * 16 + grp, r1 = r0 + 8;
    if (tg == 0) {
        g_rp[z][(size_t)h * TT + r0] = r0s;
        g_rp[z][(size_t)h * TT + r1] = r1s;
    }
    float* op = g_Op[z];
    #pragma unroll
    for (int nb = 0; nb < 16; nb++) {
        const int col = h * DV + nb * 8 + tg * 2;
        *(float2*)(op + (size_t)r0 * (HH * DV) + col) = make_float2(O[nb][0], O[nb][1]);
        *(float2*)(op + (size_t)r1 * (HH * DV) + col) = make_float2(O[nb][2], O[nb][3]);
    }
}

// ====== merge: out = (O0 + O1) / (rs0 + rs1) ================================
__global__ __launch_bounds__(256)
void merge_kernel(float* __restrict__ out) {
    const int i = blockIdx.x * 256 + threadIdx.x;   // float4 index
    if (i >= TT * HH * DV / 4) return;
    const int idx = i * 4;
    const int t = idx / (HH * DV);
    const int h = (idx % (HH * DV)) / DV;
    const float rs = g_rp[0][(size_t)h * TT + t] + g_rp[1][(size_t)h * TT + t];
    const float inv = 1.0f / rs;
    float4 a = ((const float4*)g_Op[0])[i];
    float4 b = ((const float4*)g_Op[1])[i];
    float4 r;
    r.x = (a.x + b.x) * inv;
    r.y = (a.y + b.y) * inv;
    r.z = (a.z + b.z) * inv;
    r.w = (a.w + b.w) * inv;
    ((float4*)out)[i] = r;
}

// ===================== launch =====================
extern "C" void kernel_launch(void* const* d_in, const int* in_sizes, int n_in,
                              void* d_out, int out_size) {
    const float* q    = (const float*)d_in[0];   // (1024, 16, 192)
    const float* kv   = (const float*)d_in[1];   // (8192, 576)
    const float* w_kc = (const float*)d_in[2];   // (16, 128, 512)
    const float* w_vc = (const float*)d_in[3];   // (16, 512, 128)
    float* out = (float*)d_out;                  // (1024, 2048)
    (void)in_sizes; (void)n_in; (void)out_size;

    cudaFuncSetAttribute(proj_fused, cudaFuncAttributeMaxDynamicSharedMemorySize, PJ_SMEM);
    cudaFuncSetAttribute(attn_mma, cudaFuncAttributeMaxDynamicSharedMemorySize, AT_SMEM);

    split_kernel<<<(N1 + N2 + N3 + 255) / 256, 256>>>(kv, w_kc, w_vc);

    dim3 pgrid(SS / 128, HH);
    proj_fused<<<pgrid, 256, PJ_SMEM>>>();

    dim3 agrid(TT / QROWS, HH, NSPLIT);   // (16, 16, 2) = 512 CTAs
    attn_mma<<<agrid, 128, AT_SMEM>>>(q);

    merge_kernel<<<(TT * HH * DV / 4 + 255) / 256, 256>>>(out);
}

// round 16
// speedup vs baseline: 1.0555x; 1.0306x over previous
#include <cuda_runtime.h>
#include <cuda_fp16.h>
#include <cstdint>

#define TT 1024
#define HH 16
#define SS 8192
#define DKA 128     // absorbed dims
#define DR 64       // rope dims
#define DV 128
#define LORA 512
#define KV_W 576
#define SN 32
#define NT (SS / SN)
#define QSCALE 0.1041216338861046f    // (1/sqrt(192)) * log2(e)

// fp16 inputs + projected operands
__device__ __half g_kvh[(size_t)SS * KV_W];
__device__ __half g_wkh[(size_t)HH * DKA * LORA];
__device__ __half g_wvh[(size_t)HH * LORA * DV];
__device__ __half g_Rh[(size_t)SS * DR];         // shared rope K
__device__ __half g_K[(size_t)HH * SS * DKA];    // absorbed K
__device__ __half g_V[(size_t)HH * SS * DV];     // absorbed V

// ===================== helpers =====================
__device__ __forceinline__ uint32_t smem_u32(const void* p) {
    uint32_t a;
    asm("{ .reg .u64 t; cvta.to.shared.u64 t, %1; cvt.u32.u64 %0, t; }" : "=r"(a) : "l"(p));
    return a;
}
__device__ __forceinline__ void ldsm4(uint32_t* r, uint32_t a) {
    asm volatile("ldmatrix.sync.aligned.m8n8.x4.shared.b16 {%0,%1,%2,%3}, [%4];"
        : "=r"(r[0]), "=r"(r[1]), "=r"(r[2]), "=r"(r[3]) : "r"(a));
}
__device__ __forceinline__ void ldsm4t(uint32_t* r, uint32_t a) {
    asm volatile("ldmatrix.sync.aligned.m8n8.x4.trans.shared.b16 {%0,%1,%2,%3}, [%4];"
        : "=r"(r[0]), "=r"(r[1]), "=r"(r[2]), "=r"(r[3]) : "r"(a));
}
__device__ __forceinline__ void mma16816h(float* d, const uint32_t* a, const uint32_t* b) {
    asm volatile("mma.sync.aligned.m16n8k16.row.col.f32.f16.f16.f32 "
        "{%0,%1,%2,%3}, {%4,%5,%6,%7}, {%8,%9}, {%0,%1,%2,%3};"
        : "+f"(d[0]), "+f"(d[1]), "+f"(d[2]), "+f"(d[3])
        : "r"(a[0]), "r"(a[1]), "r"(a[2]), "r"(a[3]), "r"(b[0]), "r"(b[1]));
}
__device__ __forceinline__ float ex2f(float x) {
    float r;
    asm("ex2.approx.f32 %0, %1;" : "=f"(r) : "f"(x));
    return r;
}
__device__ __forceinline__ void cp16(uint32_t dst, const void* src) {
    asm volatile("cp.async.cg.shared.global [%0], [%1], 16;" :: "r"(dst), "l"(src));
}
#define CP_COMMIT() asm volatile("cp.async.commit_group;" ::: "memory")
#define CP_WAIT0()  asm volatile("cp.async.wait_group 0;" ::: "memory")
#define CP_WAIT1()  asm volatile("cp.async.wait_group 1;" ::: "memory")
#define CP_WAIT2()  asm volatile("cp.async.wait_group 2;" ::: "memory")

// PDL (programmatic dependent launch)
__device__ __forceinline__ void gdc_wait()   { asm volatile("griddepcontrol.wait;" ::: "memory"); }
__device__ __forceinline__ void gdc_launch() { asm volatile("griddepcontrol.launch_dependents;"); }

// ===================== split kernel (fp32 -> fp16) =====================
#define N1 (SS * KV_W / 4)
#define N2 (HH * DKA * LORA / 4)
#define N3 (HH * LORA * DV / 4)

__global__ __launch_bounds__(256)
void split_kernel(const float* __restrict__ kv, const float* __restrict__ wk,
                  const float* __restrict__ wv) {
    gdc_launch();
    const int i = blockIdx.x * 256 + threadIdx.x;
    if (i < N1) {
        float4 v = ((const float4*)kv)[i];
        __half2 a = __floats2half2_rn(v.x, v.y);
        __half2 b = __floats2half2_rn(v.z, v.w);
        ((__half2*)g_kvh)[2 * i] = a; ((__half2*)g_kvh)[2 * i + 1] = b;
        int c = (i * 4) % KV_W;
        if (c >= LORA) {
            int s = (i * 4) / KV_W;
            int o = s * DR + (c - LORA);
            ((__half2*)g_Rh)[o / 2]     = a;
            ((__half2*)g_Rh)[o / 2 + 1] = b;
        }
    } else if (i < N1 + N2) {
        int j = i - N1;
        float4 v = ((const float4*)wk)[j];
        __half2 a = __floats2half2_rn(v.x, v.y);
        __half2 b = __floats2half2_rn(v.z, v.w);
        ((__half2*)g_wkh)[2 * j] = a; ((__half2*)g_wkh)[2 * j + 1] = b;
    } else if (i < N1 + N2 + N3) {
        int j = i - N1 - N2;
        float4 v = ((const float4*)wv)[j];
        __half2 a = __floats2half2_rn(v.x, v.y);
        __half2 b = __floats2half2_rn(v.z, v.w);
        ((__half2*)g_wvh)[2 * j] = a; ((__half2*)g_wvh)[2 * j + 1] = b;
    }
}

// ========== fused projection (round-10 exact): shares the kv_lora A tile ====
#define PSTR 80
#define PJ_A  0
#define PJ_BK (128 * PSTR)                  // 10240
#define PJ_BV (2 * 128 * PSTR)              // 20480
#define PJ_BVSTR 272
#define PJ_STAGE (PJ_BV + 32 * PJ_BVSTR)    // 29184
#define PJ_SMEM (2 * PJ_STAGE)              // 58368

__global__ __launch_bounds__(256)
void proj_fused() {
    extern __shared__ __align__(16) char smp[];
    const uint32_t sb = smem_u32(smp);
    const int tid = threadIdx.x, lane = tid & 31, wp = tid >> 5;
    const int grp = lane >> 2, tg = lane & 3;
    const int h = blockIdx.y, s0 = blockIdx.x * 128;

    const __half* Akv = g_kvh + (size_t)s0 * KV_W;
    const __half* BK  = g_wkh + (size_t)h * DKA * LORA;
    const __half* BV  = g_wvh + (size_t)h * LORA * DV;
    const int lr = tid >> 1;
    const int br = tid >> 3, bcb = (tid & 7) * 2;

    // wait for split_kernel's outputs before the first staged load
    gdc_wait();
    gdc_launch();   // let attention begin launching early (it waits before g_K/g_V reads)

    #define PJ_LOAD(stage, kt) do { \
        uint32_t base_ = sb + (stage) * PJ_STAGE; \
        _Pragma("unroll") \
        for (int j_ = 0; j_ < 2; j_++) { \
            int c16_ = (tid & 1) * 2 + j_; \
            cp16(base_ + PJ_A  + lr * PSTR + c16_ * 16, Akv + (size_t)lr * KV_W + (kt) + c16_ * 8); \
            cp16(base_ + PJ_BK + lr * PSTR + c16_ * 16, BK  + (size_t)lr * LORA + (kt) + c16_ * 8); \
            int b16_ = bcb + j_; \
            cp16(base_ + PJ_BV + br * PJ_BVSTR + b16_ * 16, BV + (size_t)((kt) + br) * DV + b16_ * 8); \
        } \
    } while (0)

    PJ_LOAD(0, 0); CP_COMMIT();

    float accK[16][4], accV[16][4];
    #pragma unroll
    for (int i = 0; i < 16; i++)
        #pragma unroll
        for (int j = 0; j < 4; j++) { accK[i][j] = 0.f; accV[i][j] = 0.f; }

    const uint32_t aoff  = (uint32_t)((wp * 16 + (lane & 15)) * PSTR + (lane >> 4) * 16);
    const uint32_t bkoff = (uint32_t)(((lane & 7) + ((lane >> 4) & 1) * 8) * PSTR + ((lane >> 3) & 1) * 16);
    const uint32_t bvoff = (uint32_t)(((lane & 7) + ((lane >> 3) & 1) * 8) * PJ_BVSTR + ((lane >> 4) & 1) * 16);

    for (int c = 0; c < 16; c++) {
        if (c + 1 < 16) { PJ_LOAD((c + 1) & 1, (c + 1) * 32); CP_COMMIT(); CP_WAIT1(); }
        else { CP_WAIT0(); }
        __syncthreads();
        const uint32_t base = sb + (c & 1) * PJ_STAGE;
        #pragma unroll
        for (int ks = 0; ks < 2; ks++) {
            uint32_t a[4];
            ldsm4(a, base + PJ_A + aoff + ks * 32);
            #pragma unroll
            for (int np = 0; np < 8; np++) {
                uint32_t bk[4], bv[4];
                ldsm4(bk, base + PJ_BK + bkoff + np * 16 * PSTR + ks * 32);
                mma16816h(accK[np * 2],     a, bk);
                mma16816h(accK[np * 2 + 1], a, bk + 2);
                ldsm4t(bv, base + PJ_BV + bvoff + ks * 16 * PJ_BVSTR + np * 32);
                mma16816h(accV[np * 2],     a, bv);
                mma16816h(accV[np * 2 + 1], a, bv + 2);
            }
        }
        __syncthreads();
    }

    const int r0 = s0 + wp * 16 + grp, r1 = r0 + 8;
    #pragma unroll
    for (int nb = 0; nb < 16; nb++) {
        int col = nb * 8 + tg * 2;
        __half2 k0 = __floats2half2_rn(accK[nb][0], accK[nb][1]);
        __half2 k1 = __floats2half2_rn(accK[nb][2], accK[nb][3]);
        *(__half2*)(g_K + ((size_t)h * SS + r0) * DKA + col) = k0;
        *(__half2*)(g_K + ((size_t)h * SS + r1) * DKA + col) = k1;
        __half2 v0 = __floats2half2_rn(accV[nb][0], accV[nb][1]);
        __half2 v1 = __floats2half2_rn(accV[nb][2], accV[nb][3]);
        *(__half2*)(g_V + ((size_t)h * SS + r0) * DV + col) = v0;
        *(__half2*)(g_V + ((size_t)h * SS + r1) * DV + col) = v1;
    }
}

// ====== attention: 64q CTAs, 4 slots, 1 barrier/tile, fp32 ex2 ==============
// PDL: Q prologue (reads only q, writes smem) runs BEFORE griddepcontrol.wait;
// all g_K/g_V/g_Rh reads happen after.
#define QROWS 64
#define KSTR2 400
#define VSTR2 304                       // 144 cols (128 V + ones + pad)
#define AT_K 0
#define AT_V (SN * KSTR2)               // 12800
#define AT_STG (AT_V + SN * VSTR2)      // 22528
#define AT_Q (2 * AT_STG)               // Q overlay in slots 2-3 region
#define AT_SMEM (4 * AT_STG)            // 90112

__device__ __forceinline__ void load_stage(uint32_t sb, int h, int s0, int slot, int tid) {
    const uint32_t base = sb + (uint32_t)slot * AT_STG;
    const __half* gk = g_K + ((size_t)h * SS + s0) * DKA;
    const __half* gr = g_Rh + (size_t)s0 * DR;
    const __half* gv = g_V + ((size_t)h * SS + s0) * DV;
    #pragma unroll
    for (int i = 0; i < 6; i++) {
        int idx = tid + i * 128;
        int r = idx / 24, c = idx - r * 24;
        if (c < 16) cp16(base + AT_K + r * KSTR2 + c * 16, gk + (size_t)r * DKA + c * 8);
        else        cp16(base + AT_K + r * KSTR2 + c * 16, gr + (size_t)r * DR + (c - 16) * 8);
    }
    #pragma unroll
    for (int i = 0; i < 4; i++) {
        int idx = tid + i * 128;
        int r = idx >> 4, c = idx & 15;
        cp16(base + AT_V + r * VSTR2 + c * 16, gv + (size_t)r * DV + c * 8);
    }
}

__global__ __launch_bounds__(128, 2)
void attn_mma(const float* __restrict__ q, float* __restrict__ out) {
    extern __shared__ __align__(16) char sma[];
    const uint32_t sb = smem_u32(sma);
    const int tid = threadIdx.x, lane = tid & 31, wp = tid >> 5;
    const int grp = lane >> 2, tg = lane & 3;
    const int h = blockIdx.y, t0 = blockIdx.x * QROWS;

    // ---- pre-wait prologue: depends only on q ----
    {
        const int r = tid >> 1, half = tid & 1;
        const float* qp = q + (size_t)(t0 + r) * (HH * (DKA + DR)) + (size_t)h * (DKA + DR) + half * 96;
        uint32_t* pH = (uint32_t*)(sma + AT_Q + r * KSTR2 + half * 192);
        #pragma unroll
        for (int i = 0; i < 24; i++) {
            float4 v = *(const float4*)(qp + i * 4);
            __half2 a = __floats2half2_rn(v.x * QSCALE, v.y * QSCALE);
            __half2 b = __floats2half2_rn(v.z * QSCALE, v.w * QSCALE);
            pH[2 * i]     = *(uint32_t*)&a;
            pH[2 * i + 1] = *(uint32_t*)&b;
        }
    }
    __syncthreads();

    uint32_t qf[12][4];
    {
        const uint32_t qa = sb + AT_Q + (uint32_t)((wp * 16 + (lane & 15)) * KSTR2 + (lane >> 4) * 16);
        #pragma unroll
        for (int ks = 0; ks < 12; ks++) ldsm4(qf[ks], qa + ks * 32);
    }
    // all warps must finish reading Q fragments before the ones-init below
    // overwrites parts of the Q overlay region.
    __syncthreads();

    // ones-column init: all 4 slots, V cols 128..143 (col 128 = 1.0)
    {
        const __half2 one0 = __halves2half2(__float2half(1.f), __float2half(0.f));
        const __half2 zero = __halves2half2(__float2half(0.f), __float2half(0.f));
        #pragma unroll
        for (int i = 0; i < 8; i++) {
            int idx = tid + i * 128;           // 1024 = 4 slots * 32 rows * 8 half2
            int slot = idx >> 8;
            int rem = idx & 255;
            int r = rem >> 3, c2 = rem & 7;
            *(__half2*)(sma + slot * AT_STG + AT_V + r * VSTR2 + 256 + c2 * 4)
                = (c2 == 0) ? one0 : zero;
        }
    }
    __syncthreads();

    // ---- wait for proj (transitively split), then start K/V pipeline ----
    gdc_wait();
    load_stage(sb, h, 0, 0, tid); CP_COMMIT();
    load_stage(sb, h, SN, 1, tid); CP_COMMIT();
    load_stage(sb, h, 2 * SN, 2, tid); CP_COMMIT();

    float O[18][4];
    #pragma unroll
    for (int i = 0; i < 18; i++)
        #pragma unroll
        for (int j = 0; j < 4; j++) O[i][j] = 0.f;

    const uint32_t kboff = (uint32_t)(((lane & 7) + ((lane >> 4) & 1) * 8) * KSTR2 + ((lane >> 3) & 1) * 16);
    const uint32_t vboff = (uint32_t)(((lane & 7) + ((lane >> 3) & 1) * 8) * VSTR2 + ((lane >> 4) & 1) * 16);

    for (int t = 0; t < NT; t++) {
        CP_WAIT2();
        __syncthreads();
        const uint32_t base = sb + (uint32_t)(t & 3) * AT_STG;

        // MMA1: scores (log2-domain; QSCALE folded in)
        float S[4][4];
        #pragma unroll
        for (int i = 0; i < 4; i++)
            #pragma unroll
            for (int j = 0; j < 4; j++) S[i][j] = 0.f;

        #pragma unroll
        for (int ks = 0; ks < 12; ks++) {
            #pragma unroll
            for (int np = 0; np < 2; np++) {
                uint32_t b[4];
                ldsm4(b, base + AT_K + kboff + np * 16 * KSTR2 + ks * 32);
                mma16816h(S[np * 2],     qf[ks], b);
                mma16816h(S[np * 2 + 1], qf[ks], b + 2);
            }
        }

        // softmax: p = 2^S in fp32 (MUFU), then pack to fp16 A-fragments
        uint32_t ph[2][4];
        #pragma unroll
        for (int kk = 0; kk < 2; kk++) {
            #pragma unroll
            for (int sub = 0; sub < 2; sub++) {
                float* c = S[2 * kk + sub];
                float e0 = ex2f(c[0]);
                float e1 = ex2f(c[1]);
                float e2 = ex2f(c[2]);
                float e3 = ex2f(c[3]);
                __half2 p0 = __floats2half2_rn(e0, e1);
                __half2 p1 = __floats2half2_rn(e2, e3);
                ph[kk][sub * 2]     = *(uint32_t*)&p0;
                ph[kk][sub * 2 + 1] = *(uint32_t*)&p1;
            }
        }

        // MMA2: O += P * V  (np=8 block carries the ones column -> row sums)
        #pragma unroll
        for (int kk = 0; kk < 2; kk++) {
            #pragma unroll
            for (int np = 0; np < 9; np++) {
                uint32_t v[4];
                ldsm4t(v, base + AT_V + vboff + kk * 16 * VSTR2 + np * 32);
                mma16816h(O[np * 2],     ph[kk], v);
                mma16816h(O[np * 2 + 1], ph[kk], v + 2);
            }
        }
        // no tail barrier: top-of-tile barrier at t proves all warps finished t-1,
        // and slot (t+3)&3 == (t-1)&3 was last read at t-1.
        if (t + 3 < NT) load_stage(sb, h, (t + 3) * SN, (t + 3) & 3, tid);
        CP_COMMIT();
    }

    // row sums from the tensor-core ones-column: block 16, col 128
    const float r0s = __shfl_sync(0xffffffffu, O[16][0], lane & ~3);
    const float r1s = __shfl_sync(0xffffffffu, O[16][2], lane & ~3);
    const float i0 = 1.0f / r0s, i1 = 1.0f / r1s;

    const int r0 = t0 + wp * 16 + grp, r1 = r0 + 8;
    #pragma unroll
    for (int nb = 0; nb < 16; nb++) {
        const int col = h * DV + nb * 8 + tg * 2;
        float2 v0 = make_float2(O[nb][0] * i0, O[nb][1] * i0);
        float2 v1 = make_float2(O[nb][2] * i1, O[nb][3] * i1);
        *(float2*)(out + (size_t)r0 * (HH * DV) + col) = v0;
        *(float2*)(out + (size_t)r1 * (HH * DV) + col) = v1;
    }
}

// ===================== launch =====================
extern "C" void kernel_launch(void* const* d_in, const int* in_sizes, int n_in,
                              void* d_out, int out_size) {
    const float* q    = (const float*)d_in[0];   // (1024, 16, 192)
    const float* kv   = (const float*)d_in[1];   // (8192, 576)
    const float* w_kc = (const float*)d_in[2];   // (16, 128, 512)
    const float* w_vc = (const float*)d_in[3];   // (16, 512, 128)
    float* out = (float*)d_out;                  // (1024, 2048)
    (void)in_sizes; (void)n_in; (void)out_size;

    cudaFuncSetAttribute(proj_fused, cudaFuncAttributeMaxDynamicSharedMemorySize, PJ_SMEM);
    cudaFuncSetAttribute(attn_mma, cudaFuncAttributeMaxDynamicSharedMemorySize, AT_SMEM);

    split_kernel<<<(N1 + N2 + N3 + 255) / 256, 256>>>(kv, w_kc, w_vc);

    cudaLaunchAttribute pdl;
    pdl.id = cudaLaunchAttributeProgrammaticStreamSerialization;
    pdl.val.programmaticStreamSerializationAllowed = 1;

    {   // proj (dependent of split)
        cudaLaunchConfig_t cfg = {};
        cfg.gridDim = dim3(SS / 128, HH);
        cfg.blockDim = dim3(256);
        cfg.dynamicSmemBytes = PJ_SMEM;
        cfg.stream = 0;
        cfg.attrs = &pdl;
        cfg.numAttrs = 1;
        cudaLaunchKernelEx(&cfg, proj_fused);
    }
    {   // attention (dependent of proj)
        cudaLaunchConfig_t cfg = {};
        cfg.gridDim = dim3(TT / QROWS, HH);
        cfg.blockDim = dim3(128);
        cfg.dynamicSmemBytes = AT_SMEM;
        cfg.stream = 0;
        cfg.attrs = &pdl;
        cfg.numAttrs = 1;
        cudaLaunchKernelEx(&cfg, attn_mma, q, out);
    }
}